// round 2
// baseline (speedup 1.0000x reference)
#include <cuda_runtime.h>
#include <cstdint>

// Problem constants
static constexpr int B  = 16;
static constexpr int H  = 128;
static constexpr int W  = 128;
static constexpr int C  = 64;                 // Cin == Cout == 64
static constexpr int NTOT = B * H * W * C;    // 16,777,216
static constexpr float DT  = 0.2f;
static constexpr float EPS = 1e-3f;

// Scratch: f = conv1 output (also "h" initial state). 64 MB, static device global.
__device__ float d_f_buf[NTOT];

// ---------------------------------------------------------------------------
// Kernel 1/2: 3x3 SAME conv, NHWC, with fused inference-BN + ReLU on the input.
// One block = one (b, y) full row of 128 pixels x 64 couts.
// 256 threads: thread t -> 4 pixels (t>>3)*4.. and 8 couts (t&7)*8..
// SMEM: input tile [3][130][65] (pad 65 kills bank conflicts), padded to a
// 16-byte boundary (25350 -> 25352 floats: float4 alignment of the weight
// banks — R1's misaligned-address bug), then double-buffered per-tap weights
// [2][64*64], BN scale/shift [64].
// ---------------------------------------------------------------------------
static constexpr int S_IN_FLOATS = 25352;      // 3*130*65 = 25350, pad to /4
static constexpr int CONV_SMEM_FLOATS = S_IN_FLOATS + 2 * 4096 + 128;
static constexpr int CONV_SMEM_BYTES  = CONV_SMEM_FLOATS * 4;   // 134,688 B

__global__ __launch_bounds__(256, 1)
void conv3x3_bnrelu(const float* __restrict__ in,
                    const float* __restrict__ wgt,     // [3][3][64][64] HWIO
                    const float* __restrict__ gamma,
                    const float* __restrict__ beta,
                    const float* __restrict__ mean,
                    const float* __restrict__ var,
                    float* __restrict__ out)
{
    extern __shared__ float smem[];
    float* s_in    = smem;                         // [3][130][65]
    float* s_w     = smem + S_IN_FLOATS;           // [2][4096], 16B-aligned
    float* s_scale = s_w + 2 * 4096;               // [64]
    float* s_shift = s_scale + 64;                 // [64]

    const int tid = threadIdx.x;
    const int y   = blockIdx.x;
    const int b   = blockIdx.y;

    if (tid < 64) {
        float sc = gamma[tid] * rsqrtf(var[tid] + EPS);
        s_scale[tid] = sc;
        s_shift[tid] = beta[tid] - mean[tid] * sc;
    }
    __syncthreads();

    // ---- fill activated input tile (zero halo: SAME padding applies to the
    // activated tensor, so halo is literally 0) ----
    const float* inb = in + ((size_t)b * H) * W * C;
    for (int e = tid; e < 3 * 130 * C; e += 256) {
        int r   = e / (130 * C);
        int rem = e - r * (130 * C);
        int px  = rem >> 6;           // 0..129
        int ci  = rem & 63;
        int yy  = y + r - 1;
        int xx  = px - 1;
        float v = 0.f;
        if ((unsigned)yy < (unsigned)H && (unsigned)xx < (unsigned)W) {
            float t = inb[((size_t)yy * W + xx) * C + ci] * s_scale[ci] + s_shift[ci];
            v = fmaxf(t, 0.f);
        }
        s_in[(r * 130 + px) * 65 + ci] = v;
    }

    // ---- prologue: tap-0 weights into buffer 0 ----
    const float4* w4 = reinterpret_cast<const float4*>(wgt);
    float4* s_w4 = reinterpret_cast<float4*>(s_w);
    float4 wreg[4];
#pragma unroll
    for (int j = 0; j < 4; ++j) wreg[j] = w4[tid + j * 256];
#pragma unroll
    for (int j = 0; j < 4; ++j) s_w4[tid + j * 256] = wreg[j];
    __syncthreads();

    const int co8 = (tid & 7);        // cout block: couts co8*8 .. co8*8+7
    const int px0 = (tid >> 3) * 4;   // pixels px0 .. px0+3

    float acc[4][8];
#pragma unroll
    for (int j = 0; j < 4; ++j)
#pragma unroll
        for (int k = 0; k < 8; ++k) acc[j][k] = 0.f;

    for (int tap = 0; tap < 9; ++tap) {
        const int cur = tap & 1;
        // prefetch next tap's weights into registers (overlaps compute)
        if (tap + 1 < 9) {
#pragma unroll
            for (int j = 0; j < 4; ++j)
                wreg[j] = w4[(tap + 1) * 1024 + tid + j * 256];
        }
        const int ty = tap / 3;
        const int tx = tap - ty * 3;
        // s_in pixel index for output pixel x with tap tx is (x + tx - 1) + 1 = x + tx
        const float* sin_row = s_in + (ty * 130 + px0 + tx) * 65;
        const float4* swc = reinterpret_cast<const float4*>(s_w + cur * 4096) + co8 * 2;

#pragma unroll 4
        for (int ci = 0; ci < 64; ++ci) {
            float iv0 = sin_row[ci];
            float iv1 = sin_row[ci + 65];
            float iv2 = sin_row[ci + 130];
            float iv3 = sin_row[ci + 195];
            float4 wa = swc[(ci << 4)];
            float4 wb = swc[(ci << 4) + 1];
            float wv[8] = {wa.x, wa.y, wa.z, wa.w, wb.x, wb.y, wb.z, wb.w};
            float iv[4] = {iv0, iv1, iv2, iv3};
#pragma unroll
            for (int j = 0; j < 4; ++j)
#pragma unroll
                for (int k = 0; k < 8; ++k)
                    acc[j][k] = fmaf(iv[j], wv[k], acc[j][k]);
        }
        __syncthreads();
        if (tap + 1 < 9) {
            float4* dst = reinterpret_cast<float4*>(s_w + (1 - cur) * 4096);
#pragma unroll
            for (int j = 0; j < 4; ++j) dst[tid + j * 256] = wreg[j];
            __syncthreads();
        }
    }

    // ---- epilogue: vectorized stores ----
    float* ob = out + (((size_t)b * H + y) * W) * C;
#pragma unroll
    for (int j = 0; j < 4; ++j) {
        float4 v0 = make_float4(acc[j][0], acc[j][1], acc[j][2], acc[j][3]);
        float4 v1 = make_float4(acc[j][4], acc[j][5], acc[j][6], acc[j][7]);
        size_t off = (size_t)(px0 + j) * C + co8 * 8;
        *reinterpret_cast<float4*>(ob + off)     = v0;
        *reinterpret_cast<float4*>(ob + off + 4) = v1;
    }
}

// ---------------------------------------------------------------------------
// Kernel 3: fully-fused diffusion.
// One block = one (b, y) row (128 px x 64 ch = 8192 floats = 32 KB/array).
// SMEM: h-ping, h-pong, f(raw), Ax(=DT*g), Bx2(=2*DT*Dx), By2(=2*DT*Dy),
// E2(=2*E). 7 x 32 KB = 229,376 B dynamic smem.
// Rolls: W-wrap = (i +/- 64) & 8191; channel-wrap rotates low 6 bits.
// Sobel uses REFLECT on rows y+-1 (read from global f, L1-cached) and on x.
// ---------------------------------------------------------------------------
static constexpr int DIFF_SMEM_BYTES = 7 * 8192 * 4;   // 229,376 B

__global__ __launch_bounds__(256, 1)
void diffuse_fused(const float* __restrict__ f,
                   float* __restrict__ outh,       // d_out[0:N)
                   const float* __restrict__ g,    // d_out[N:2N) (conv2 result)
                   const float* __restrict__ gamma,
                   const float* __restrict__ beta,
                   const float* __restrict__ mean,
                   const float* __restrict__ var)
{
    extern __shared__ float sm[];
    float* Abuf = sm;                // h ping
    float* Bbuf = sm + 8192;         // h pong
    float* F    = sm + 16384;        // raw f row
    float* G    = sm + 24576;        // raw g, later *= DT  (Ax == Ay)
    float* BX   = sm + 32768;        // 2*DT*Dx
    float* BY   = sm + 40960;        // 2*DT*Dy
    float* E2   = sm + 49152;        // 2*E
    __shared__ float sc[64], sh[64];

    const int tid = threadIdx.x;
    const int y   = blockIdx.x;
    const int b   = blockIdx.y;

    if (tid < 64) {
        float s = gamma[tid] * rsqrtf(var[tid] + EPS);
        sc[tid] = s;
        sh[tid] = beta[tid] - mean[tid] * s;
    }

    const size_t rowbase = (((size_t)b * H) + y) * W * C;
    const float* frow = f + rowbase;
    const float* grow = g + rowbase;
    for (int i = tid; i < 8192; i += 256) {
        float v = frow[i];
        F[i] = v;
        Abuf[i] = v;
        G[i] = grow[i];
    }
    __syncthreads();

    // Sobel rows with REFLECT (no edge repeat): -1 -> 1, H -> H-2
    const int ym = (y == 0) ? 1 : y - 1;
    const int yp = (y == H - 1) ? H - 2 : y + 1;
    const float* fm = f + ((((size_t)b * H) + ym) * W) * C;
    const float* fp = f + ((((size_t)b * H) + yp) * W) * C;

    for (int i = tid; i < 8192; i += 256) {
        const int x = i >> 6;
        const int c = i & 63;
        // --- E = (ux + vy) * DT ; rolls WRAP ---
        const int ixm = (i + 8192 - 64) & 8191;
        const int ixp = (i + 64) & 8191;
        const int icm = (i & ~63) | ((c + 63) & 63);
        const int icp = (i & ~63) | ((c + 1) & 63);
        E2[i] = DT * ((G[ixm] - G[ixp]) + (G[icm] - G[icp]));

        // --- Sobel with REFLECT in x ---
        const int xm = (x == 0) ? 1 : x - 1;
        const int xp = (x == W - 1) ? W - 2 : x + 1;
        float am = fm[xm * 64 + c], a0 = fm[x * 64 + c], ap = fm[xp * 64 + c];
        float bm = fp[xm * 64 + c], b0 = fp[x * 64 + c], bp = fp[xp * 64 + c];
        float dy = (bm + 2.f * b0 + bp) - (am + 2.f * a0 + ap);
        float fxm = F[xm * 64 + c];
        float fxp = F[xp * 64 + c];
        float dx = (ap - am) + 2.f * (fxp - fxm) + (bp - bm);
        // Dx = 1/(dy^2/4 + 1) (faithful swap), Bx2 = 2*DT*Dx
        BX[i] = (2.f * DT) / (0.25f * dy * dy + 1.f);
        BY[i] = (2.f * DT) / (0.25f * dx * dx + 1.f);
    }
    __syncthreads();
    for (int i = tid; i < 8192; i += 256) G[i] *= DT;   // Ax = Ay = DT*g
    __syncthreads();

    // --- K = 5 diffusion iterations, ping-pong in SMEM ---
    float* hprev = Abuf;
    float* hcur  = Abuf;
#pragma unroll
    for (int k = 0; k < 5; ++k) {
        float* hnext = (hprev == hcur) ? Bbuf : hprev;
        for (int i = tid; i < 8192; i += 256) {
            const int c   = i & 63;
            const int ixm = (i + 8192 - 64) & 8191;
            const int ixp = (i + 64) & 8191;
            const int icm = (i & ~63) | ((c + 63) & 63);
            const int icp = (i & ~63) | ((c + 1) & 63);
            float ax = G[i], bx = BX[i], by = BY[i];
            float s = (1.f - bx - by) * hprev[i];
            s = fmaf(-E2[i], hcur[i], s);
            s = fmaf(bx - ax, hcur[ixm], s);
            s = fmaf(bx + ax, hcur[ixp], s);
            s = fmaf(by - ax, hcur[icm], s);
            s = fmaf(by + ax, hcur[icp], s);
            s = fmaf(2.f * DT, F[i], s);
            hnext[i] = s / (1.f + bx + by);
        }
        __syncthreads();
        float* t = hcur; hcur = hnext; hprev = t;
    }

    // --- epilogue: relu(bn_o(h)) -> d_out first half ---
    float* o = outh + rowbase;
    for (int i = tid; i < 8192; i += 256) {
        const int c = i & 63;
        o[i] = fmaxf(fmaf(hcur[i], sc[c], sh[c]), 0.f);
    }
}

// ---------------------------------------------------------------------------
extern "C" void kernel_launch(void* const* d_in, const int* in_sizes, int n_in,
                              void* d_out, int out_size)
{
    const float* x   = (const float*)d_in[0];
    const float* f_w = (const float*)d_in[1];
    const float* g_w = (const float*)d_in[2];
    const float* bnf_gamma = (const float*)d_in[3];
    const float* bnf_beta  = (const float*)d_in[4];
    const float* bnf_mean  = (const float*)d_in[5];
    const float* bnf_var   = (const float*)d_in[6];
    const float* bng_gamma = (const float*)d_in[7];
    const float* bng_beta  = (const float*)d_in[8];
    const float* bng_mean  = (const float*)d_in[9];
    const float* bng_var   = (const float*)d_in[10];
    const float* bno_gamma = (const float*)d_in[11];
    const float* bno_beta  = (const float*)d_in[12];
    const float* bno_mean  = (const float*)d_in[13];
    const float* bno_var   = (const float*)d_in[14];

    float* out = (float*)d_out;           // [0:N) = h, [N:2N) = g

    float* fptr = nullptr;
    cudaGetSymbolAddress((void**)&fptr, d_f_buf);

    cudaFuncSetAttribute(conv3x3_bnrelu,
                         cudaFuncAttributeMaxDynamicSharedMemorySize,
                         CONV_SMEM_BYTES);
    cudaFuncSetAttribute(diffuse_fused,
                         cudaFuncAttributeMaxDynamicSharedMemorySize,
                         DIFF_SMEM_BYTES);

    dim3 grid(H, B);
    dim3 blk(256);

    // f = conv(relu(bn_f(x)), f_w)
    conv3x3_bnrelu<<<grid, blk, CONV_SMEM_BYTES>>>(
        x, f_w, bnf_gamma, bnf_beta, bnf_mean, bnf_var, fptr);

    // g = conv(relu(bn_g(f)), g_w)  -> written straight into d_out[N:2N)
    conv3x3_bnrelu<<<grid, blk, CONV_SMEM_BYTES>>>(
        fptr, g_w, bng_gamma, bng_beta, bng_mean, bng_var, out + NTOT);

    // fused sobel + coefficients + 5 diffusion iters + bn_o/relu -> d_out[0:N)
    diffuse_fused<<<grid, blk, DIFF_SMEM_BYTES>>>(
        fptr, out, out + NTOT, bno_gamma, bno_beta, bno_mean, bno_var);
}

// round 4
// speedup vs baseline: 3.4565x; 3.4565x over previous
#include <cuda_runtime.h>
#include <cuda_bf16.h>
#include <cstdint>

// ===========================================================================
// Problem constants
// ===========================================================================
static constexpr int B  = 16;
static constexpr int H  = 128;
static constexpr int W  = 128;
static constexpr int C  = 64;
static constexpr int NTOT = B * H * W * C;    // 16,777,216
static constexpr float DT  = 0.2f;
static constexpr float EPS = 1e-3f;

// Scratch
__device__ float d_f_buf[NTOT];               // conv1 output (f == h_init)
// Pre-split bf16 weights: [conv][ty][plane(hi=0,lo=1)*12800 + n*200 + k]
// n = cout (64 rows), k = tx*64 + cin (192, padded row stride 200 bf16 = 400B)
__device__ __nv_bfloat16 d_wbf[2][3][2 * 64 * 200];

// ===========================================================================
// mma.sync / ldmatrix helpers (plain-PTX, valid on .target sm_103)
// ===========================================================================
__device__ __forceinline__ uint32_t smem_u32(const void* p) {
    uint32_t a;
    asm("{ .reg .u64 t; cvta.to.shared.u64 t, %1; cvt.u32.u64 %0, t; }"
        : "=r"(a) : "l"(p));
    return a;
}

__device__ __forceinline__ void ldsm_x4(uint32_t (&r)[4], uint32_t addr) {
    asm volatile("ldmatrix.sync.aligned.m8n8.x4.shared.b16 {%0,%1,%2,%3}, [%4];"
                 : "=r"(r[0]), "=r"(r[1]), "=r"(r[2]), "=r"(r[3]) : "r"(addr));
}

__device__ __forceinline__ void mma_bf16(float (&d)[4], const uint32_t (&a)[4],
                                         uint32_t b0, uint32_t b1) {
    asm volatile(
        "mma.sync.aligned.m16n8k16.row.col.f32.bf16.bf16.f32 "
        "{%0,%1,%2,%3}, {%4,%5,%6,%7}, {%8,%9}, {%0,%1,%2,%3};"
        : "+f"(d[0]), "+f"(d[1]), "+f"(d[2]), "+f"(d[3])
        : "r"(a[0]), "r"(a[1]), "r"(a[2]), "r"(a[3]), "r"(b0), "r"(b1));
}

// ===========================================================================
// Weight prep: HWIO [3][3][64][64] -> per-ty [N=64][K=192] bf16 hi/lo split,
// rows padded to 200 bf16 (400 B) so n-rows stagger banks for ldmatrix.
// ===========================================================================
__global__ void prep_weights(const float* __restrict__ fw,
                             const float* __restrict__ gw)
{
    int idx = blockIdx.x * blockDim.x + threadIdx.x;     // 2*3*192*64 = 73728
    if (idx >= 73728) return;
    int conv = idx / 36864;  int r = idx - conv * 36864;
    int ty   = r / 12288;    r -= ty * 12288;
    int k    = r >> 6;       int n = r & 63;             // k 0..191, n = cout
    int tx   = k >> 6;       int ci = k & 63;
    const float* w = conv ? gw : fw;
    float v = w[(((ty * 3 + tx) * 64) + ci) * 64 + n];
    __nv_bfloat16 hi = __float2bfloat16_rn(v);
    __nv_bfloat16 lo = __float2bfloat16_rn(v - __bfloat162float(hi));
    __nv_bfloat16* base = &d_wbf[conv][ty][0];
    base[n * 200 + k]         = hi;
    base[12800 + n * 200 + k] = lo;
}

// ===========================================================================
// Conv via mma.sync bf16 (3-pass hi/lo split), fused input BN+ReLU.
// One block = one (b,y): M=128 pixels, N=64 couts, K=576 (looped over ty).
// 256 threads = 8 warps in a 4(m) x 2(n) grid: warp tile m32 x n32.
// SMEM: A planes [130 px][72 bf16] hi+lo (halo px 0,129 zeroed),
//       B planes [64 n][200 bf16] hi+lo for current ty.
// ===========================================================================
static constexpr int A_STRIDE = 72;                       // bf16 per pixel row
static constexpr int A_PLANE  = 130 * A_STRIDE;           // 9360 bf16
static constexpr int B_PLANE  = 64 * 200;                 // 12800 bf16
static constexpr int CONV_SMEM_BYTES = (2 * A_PLANE + 2 * B_PLANE) * 2;  // 88,640

__global__ __launch_bounds__(256, 2)
void conv_mma(const float* __restrict__ in,
              const __nv_bfloat16* __restrict__ wbase,    // d_wbf[conv]
              const float* __restrict__ gamma,
              const float* __restrict__ beta,
              const float* __restrict__ mean,
              const float* __restrict__ var,
              float* __restrict__ out)
{
    extern __shared__ __align__(16) char smem_raw[];
    __nv_bfloat16* s_ah = reinterpret_cast<__nv_bfloat16*>(smem_raw);
    __nv_bfloat16* s_al = s_ah + A_PLANE;
    __nv_bfloat16* s_b  = s_al + A_PLANE;                 // [hi 12800 | lo 12800]
    __shared__ float s_scale[64], s_shift[64];

    const int tid  = threadIdx.x;
    const int wid  = tid >> 5;
    const int lane = tid & 31;
    const int y    = blockIdx.x;
    const int b    = blockIdx.y;
    const int wm   = wid & 3;        // m32 tile: pixels wm*32..+31
    const int wn   = wid >> 2;       // n32 tile: couts  wn*32..+31

    if (tid < 64) {
        float sc = gamma[tid] * rsqrtf(var[tid] + EPS);
        s_scale[tid] = sc;
        s_shift[tid] = beta[tid] - mean[tid] * sc;
    }
    __syncthreads();

    const uint32_t ah_base = smem_u32(s_ah);
    const uint32_t al_base = smem_u32(s_al);
    const uint32_t bh_base = smem_u32(s_b);
    const uint32_t bl_base = bh_base + B_PLANE * 2;

    // lane decode for ldmatrix.x4 address generation
    const int r8  = lane & 7;
    const int sel = lane >> 3;                // 0..3
    // A: matrices (sel&1 -> m-half, sel>>1 -> k-half)
    const int a_row_off = (sel & 1) * 8 + r8;             // within m16
    const int a_kh      = (sel >> 1) * 16;                // byte offset
    // B: matrices (sel>>1 -> n-half, sel&1 -> k-half)
    const int b_n_off   = (sel >> 1) * 8 + r8;            // within n16
    const int b_kh      = (sel & 1) * 16;

    const float* inb = in + ((size_t)b * H) * W * C;

    float acc[2][4][4];
#pragma unroll
    for (int mt = 0; mt < 2; ++mt)
#pragma unroll
        for (int nt = 0; nt < 4; ++nt)
#pragma unroll
            for (int e = 0; e < 4; ++e) acc[mt][nt][e] = 0.f;

    for (int ty = 0; ty < 3; ++ty) {
        // ---- stage A: BN+ReLU+split of input row y+ty-1 into padded planes ----
        const int yy = y + ty - 1;
        const bool rowok = (unsigned)yy < (unsigned)H;
        for (int e = tid; e < 130 * 16; e += 256) {
            const int px = e >> 4;
            const int c4 = (e & 15) << 2;
            float v0 = 0.f, v1 = 0.f, v2 = 0.f, v3 = 0.f;
            if (rowok && px >= 1 && px <= 128) {
                float4 t = *reinterpret_cast<const float4*>(
                    inb + ((size_t)yy * W + (px - 1)) * C + c4);
                v0 = fmaxf(fmaf(t.x, s_scale[c4],     s_shift[c4]),     0.f);
                v1 = fmaxf(fmaf(t.y, s_scale[c4 + 1], s_shift[c4 + 1]), 0.f);
                v2 = fmaxf(fmaf(t.z, s_scale[c4 + 2], s_shift[c4 + 2]), 0.f);
                v3 = fmaxf(fmaf(t.w, s_scale[c4 + 3], s_shift[c4 + 3]), 0.f);
            }
            __nv_bfloat162 h01 = __floats2bfloat162_rn(v0, v1);
            __nv_bfloat162 h23 = __floats2bfloat162_rn(v2, v3);
            __nv_bfloat162 l01 = __floats2bfloat162_rn(
                v0 - __bfloat162float(h01.x), v1 - __bfloat162float(h01.y));
            __nv_bfloat162 l23 = __floats2bfloat162_rn(
                v2 - __bfloat162float(h23.x), v3 - __bfloat162float(h23.y));
            const int o = px * A_STRIDE + c4;
            *reinterpret_cast<__nv_bfloat162*>(s_ah + o)     = h01;
            *reinterpret_cast<__nv_bfloat162*>(s_ah + o + 2) = h23;
            *reinterpret_cast<__nv_bfloat162*>(s_al + o)     = l01;
            *reinterpret_cast<__nv_bfloat162*>(s_al + o + 2) = l23;
        }
        // ---- copy pre-split weights for this ty (hi+lo, 51,200 B) ----
        {
            const uint4* gsrc = reinterpret_cast<const uint4*>(wbase + ty * 2 * B_PLANE);
            uint4* dst = reinterpret_cast<uint4*>(s_b);
            for (int q = tid; q < 3200; q += 256) dst[q] = gsrc[q];
        }
        __syncthreads();

        // ---- 12 k-steps (3 tx x 4 ci16), 24 mma each ----
#pragma unroll
        for (int ks = 0; ks < 12; ++ks) {
            const int tx   = ks >> 2;
            const int ci16 = ks & 3;

            uint32_t afr[2][2][4];     // [mtile][plane]
#pragma unroll
            for (int mt = 0; mt < 2; ++mt) {
                const int px = wm * 32 + mt * 16 + a_row_off + tx;
                const uint32_t off = (uint32_t)(px * (A_STRIDE * 2) + ci16 * 32 + a_kh);
                ldsm_x4(afr[mt][0], ah_base + off);
                ldsm_x4(afr[mt][1], al_base + off);
            }
            uint32_t bfr[2][2][4];     // [n16 group][plane]
#pragma unroll
            for (int g = 0; g < 2; ++g) {
                const int n = wn * 32 + g * 16 + b_n_off;
                const uint32_t off = (uint32_t)(n * 400 + tx * 128 + ci16 * 32 + b_kh);
                ldsm_x4(bfr[g][0], bh_base + off);
                ldsm_x4(bfr[g][1], bl_base + off);
            }
#pragma unroll
            for (int mt = 0; mt < 2; ++mt)
#pragma unroll
                for (int nt = 0; nt < 4; ++nt) {
                    const int g = nt >> 1, h2 = (nt & 1) * 2;
                    mma_bf16(acc[mt][nt], afr[mt][0], bfr[g][0][h2], bfr[g][0][h2 + 1]);
                    mma_bf16(acc[mt][nt], afr[mt][0], bfr[g][1][h2], bfr[g][1][h2 + 1]);
                    mma_bf16(acc[mt][nt], afr[mt][1], bfr[g][0][h2], bfr[g][0][h2 + 1]);
                }
        }
        __syncthreads();
    }

    // ---- epilogue: fp32 accumulators -> NHWC output ----
    float* ob = out + (((size_t)b * H + y) * W) * C;
#pragma unroll
    for (int mt = 0; mt < 2; ++mt) {
        const int x0 = wm * 32 + mt * 16 + (lane >> 2);
        float* row0 = ob + (size_t)x0 * C;
        float* row1 = row0 + 8 * C;
#pragma unroll
        for (int nt = 0; nt < 4; ++nt) {
            const int co = wn * 32 + nt * 8 + (lane & 3) * 2;
            *reinterpret_cast<float2*>(row0 + co) = make_float2(acc[mt][nt][0], acc[mt][nt][1]);
            *reinterpret_cast<float2*>(row1 + co) = make_float2(acc[mt][nt][2], acc[mt][nt][3]);
        }
    }
}

// ===========================================================================
// Fused diffusion: 512 threads, per-element constants in registers,
// h ping-pong between two SMEM arrays for neighbor access only.
// ===========================================================================
static constexpr int DIFF_SMEM_BYTES = 7 * 8192 * 4;   // 229,376 B

__global__ __launch_bounds__(512, 1)
void diffuse_fused(const float* __restrict__ f,
                   float* __restrict__ outh,
                   const float* __restrict__ g,
                   const float* __restrict__ gamma,
                   const float* __restrict__ beta,
                   const float* __restrict__ mean,
                   const float* __restrict__ var)
{
    extern __shared__ float sm[];
    float* S0  = sm;             // F during setup, then E2
    float* S1  = sm + 8192;      // G during setup, then h pong
    float* CM  = sm + 16384;
    float* CP  = sm + 24576;
    float* CCM = sm + 32768;
    float* CCP = sm + 40960;
    float* S6  = sm + 49152;     // h ping
    __shared__ float sc[64], sh[64];

    const int tid = threadIdx.x;
    const int y   = blockIdx.x;
    const int b   = blockIdx.y;

    if (tid < 64) {
        float s = gamma[tid] * rsqrtf(var[tid] + EPS);
        sc[tid] = s;
        sh[tid] = beta[tid] - mean[tid] * s;
    }

    const size_t rowbase = (((size_t)b * H) + y) * W * C;
    const float* frow = f + rowbase;
    const float* grow = g + rowbase;
#pragma unroll
    for (int j = 0; j < 16; ++j) {
        int i = tid + j * 512;
        S0[i] = frow[i];
        S1[i] = grow[i];
    }
    __syncthreads();

    const int ym = (y == 0) ? 1 : y - 1;
    const int yp = (y == H - 1) ? H - 2 : y + 1;
    const float* fm = f + ((((size_t)b * H) + ym) * W) * C;
    const float* fp = f + ((((size_t)b * H) + yp) * W) * C;

    float c0r[16], cdr[16], cfr[16], hprev[16], hcur[16];

    // phase 2a: Sobel + coefficients (reads S0=F, S1=G)
#pragma unroll
    for (int j = 0; j < 16; ++j) {
        const int i = tid + j * 512;
        const int x = i >> 6;
        const int c = i & 63;
        const int xm = (x == 0) ? 1 : x - 1;
        const int xp = (x == W - 1) ? W - 2 : x + 1;
        float am = fm[xm * 64 + c], a0 = fm[x * 64 + c], ap = fm[xp * 64 + c];
        float bm = fp[xm * 64 + c], b0 = fp[x * 64 + c], bp = fp[xp * 64 + c];
        float dy = (bm + 2.f * b0 + bp) - (am + 2.f * a0 + ap);
        float fxm = S0[xm * 64 + c];
        float fxp = S0[xp * 64 + c];
        float dx = (ap - am) + 2.f * (fxp - fxm) + (bp - bm);
        float bx = (2.f * DT) / (0.25f * dy * dy + 1.f);   // 2*DT*Dx
        float by = (2.f * DT) / (0.25f * dx * dx + 1.f);   // 2*DT*Dy
        float ax = DT * S1[i];                             // Ax == Ay == DT*g
        CM[i]  = bx - ax;
        CP[i]  = bx + ax;
        CCM[i] = by - ax;
        CCP[i] = by + ax;
        c0r[j] = 1.f - bx - by;
        cdr[j] = 1.f / (1.f + bx + by);
        float fv = S0[i];
        cfr[j] = 2.f * DT * fv;
        hprev[j] = fv;
        hcur[j]  = fv;
        S6[i] = fv;
    }
    __syncthreads();

    // phase 2b: E2 = 2*E into S0 (reads only S1=G)
#pragma unroll
    for (int j = 0; j < 16; ++j) {
        const int i = tid + j * 512;
        const int c = i & 63;
        const int ixm = (i + 8192 - 64) & 8191;
        const int ixp = (i + 64) & 8191;
        const int icm = (i & ~63) | ((c + 63) & 63);
        const int icp = (i & ~63) | ((c + 1) & 63);
        S0[i] = DT * ((S1[ixm] - S1[ixp]) + (S1[icm] - S1[icp]));
    }
    __syncthreads();

    // K = 5 diffusion iterations; neighbors from SMEM ping-pong, own state in regs
#pragma unroll
    for (int k = 0; k < 5; ++k) {
        float* rb = (k & 1) ? S1 : S6;
        float* wb = (k & 1) ? S6 : S1;
#pragma unroll
        for (int j = 0; j < 16; ++j) {
            const int i = tid + j * 512;
            const int c = i & 63;
            const int ixm = (i + 8192 - 64) & 8191;
            const int ixp = (i + 64) & 8191;
            const int icm = (i & ~63) | ((c + 63) & 63);
            const int icp = (i & ~63) | ((c + 1) & 63);
            float s = c0r[j] * hprev[j];
            s = fmaf(-S0[i], hcur[j], s);
            s = fmaf(CM[i],  rb[ixm], s);
            s = fmaf(CP[i],  rb[ixp], s);
            s = fmaf(CCM[i], rb[icm], s);
            s = fmaf(CCP[i], rb[icp], s);
            s += cfr[j];
            s *= cdr[j];
            hprev[j] = hcur[j];
            hcur[j]  = s;
            if (k < 4) wb[i] = s;
        }
        if (k < 4) __syncthreads();
    }

    // epilogue: relu(bn_o(h)) straight from registers
    float* o = outh + rowbase;
#pragma unroll
    for (int j = 0; j < 16; ++j) {
        const int i = tid + j * 512;
        const int c = i & 63;
        o[i] = fmaxf(fmaf(hcur[j], sc[c], sh[c]), 0.f);
    }
}

// ===========================================================================
extern "C" void kernel_launch(void* const* d_in, const int* in_sizes, int n_in,
                              void* d_out, int out_size)
{
    const float* x   = (const float*)d_in[0];
    const float* f_w = (const float*)d_in[1];
    const float* g_w = (const float*)d_in[2];
    const float* bnf_gamma = (const float*)d_in[3];
    const float* bnf_beta  = (const float*)d_in[4];
    const float* bnf_mean  = (const float*)d_in[5];
    const float* bnf_var   = (const float*)d_in[6];
    const float* bng_gamma = (const float*)d_in[7];
    const float* bng_beta  = (const float*)d_in[8];
    const float* bng_mean  = (const float*)d_in[9];
    const float* bng_var   = (const float*)d_in[10];
    const float* bno_gamma = (const float*)d_in[11];
    const float* bno_beta  = (const float*)d_in[12];
    const float* bno_mean  = (const float*)d_in[13];
    const float* bno_var   = (const float*)d_in[14];

    float* out = (float*)d_out;            // [0:N) = h, [N:2N) = g

    float* fptr = nullptr;
    cudaGetSymbolAddress((void**)&fptr, d_f_buf);
    __nv_bfloat16* wptr = nullptr;
    cudaGetSymbolAddress((void**)&wptr, d_wbf);

    cudaFuncSetAttribute(conv_mma,
                         cudaFuncAttributeMaxDynamicSharedMemorySize, CONV_SMEM_BYTES);
    cudaFuncSetAttribute(diffuse_fused,
                         cudaFuncAttributeMaxDynamicSharedMemorySize, DIFF_SMEM_BYTES);

    // 1) weight transform (both convs)
    prep_weights<<<288, 256>>>(f_w, g_w);

    dim3 grid(H, B);

    // 2) f = conv(relu(bn_f(x)), f_w)
    conv_mma<<<grid, 256, CONV_SMEM_BYTES>>>(
        x, wptr, bnf_gamma, bnf_beta, bnf_mean, bnf_var, fptr);

    // 3) g = conv(relu(bn_g(f)), g_w) -> d_out[N:2N)
    conv_mma<<<grid, 256, CONV_SMEM_BYTES>>>(
        fptr, wptr + 3 * 2 * 64 * 200, bng_gamma, bng_beta, bng_mean, bng_var, out + NTOT);

    // 4) fused sobel + coefficients + 5 diffusion iters + bn_o/relu -> d_out[0:N)
    diffuse_fused<<<grid, 512, DIFF_SMEM_BYTES>>>(
        fptr, out, out + NTOT, bno_gamma, bno_beta, bno_mean, bno_var);
}